// round 8
// baseline (speedup 1.0000x reference)
#include <cuda_runtime.h>
#include <cstdint>

#define N_NODES 50000
#define N_EDGES 1000000
#define IN_DIM  128
#define HID     64
#define OUT_DIM 16
#define NCHUNK  ((N_NODES + 255) / 256)   // 196

// Scratch (device globals — no allocation allowed)
__device__ __align__(16) int   g_cnt[N_NODES];     // in-degree (w/o self loop)
__device__ __align__(16) int   g_off[N_NODES];     // CSR row offsets (exclusive)
__device__ __align__(16) int   g_cur[N_NODES];     // fill cursors
__device__ __align__(16) int   g_spine[NCHUNK];
__device__ __align__(16) int   g_esrc[N_EDGES];    // edge sources bucketed by dst
__device__ __align__(16) float g_dinv[N_NODES];
__device__ __align__(16) float g_h1[N_NODES * HID];     // hs1 = (x@W1)*dinv[row]
__device__ __align__(16) float g_z [N_NODES * HID];     // relu(dinv*agg1 + b1)
__device__ __align__(16) float g_h2[N_NODES * OUT_DIM]; // hs2 = (z@W2)*dinv[row]

// ---------------------------------------------------------------------------
__global__ void k_zero() {
    int i = blockIdx.x * blockDim.x + threadIdx.x;
    if (i < N_NODES) g_cnt[i] = 0;
}

__global__ void k_count(const int* __restrict__ dst) {
    int e = blockIdx.x * blockDim.x + threadIdx.x;
    if (e < N_EDGES) atomicAdd(&g_cnt[dst[e]], 1);
}

// Per-chunk inclusive scan -> local exclusive offsets + chunk sums; also dinv.
__global__ void k_scan_local() {
    __shared__ int sh[256];
    int t = threadIdx.x;
    int i = blockIdx.x * 256 + t;
    int c = (i < N_NODES) ? g_cnt[i] : 0;
    sh[t] = c;
    __syncthreads();
#pragma unroll
    for (int d = 1; d < 256; d <<= 1) {
        int v = (t >= d) ? sh[t - d] : 0;
        __syncthreads();
        sh[t] += v;
        __syncthreads();
    }
    if (i < N_NODES) {
        g_off[i]  = sh[t] - c;                 // local exclusive
        g_dinv[i] = rsqrtf((float)(c + 1));    // deg includes self loop
    }
    if (t == 255) g_spine[blockIdx.x] = sh[255];
}

__global__ void k_scan_spine() {
    __shared__ int sh[256];
    int t = threadIdx.x;
    int c = (t < NCHUNK) ? g_spine[t] : 0;
    sh[t] = c;
    __syncthreads();
#pragma unroll
    for (int d = 1; d < 256; d <<= 1) {
        int v = (t >= d) ? sh[t - d] : 0;
        __syncthreads();
        sh[t] += v;
        __syncthreads();
    }
    if (t < NCHUNK) g_spine[t] = sh[t] - c;    // exclusive
}

__global__ void k_scan_add() {
    int i = blockIdx.x * blockDim.x + threadIdx.x;
    if (i < N_NODES) {
        int o = g_off[i] + g_spine[i >> 8];
        g_off[i] = o;
        g_cur[i] = o;
    }
}

__global__ void k_fill(const int* __restrict__ src,
                       const int* __restrict__ dst) {
    int e = blockIdx.x * blockDim.x + threadIdx.x;
    if (e < N_EDGES) {
        int d = dst[e];
        int p = atomicAdd(&g_cur[d], 1);
        g_esrc[p] = src[e];
    }
}

// ---------------------------------------------------------------------------
// hs1 = (x @ W1) * dinv[row].  block = 256 = 4 rows x 64 cols
__global__ void k_gemm1(const float* __restrict__ x, const float* __restrict__ W1) {
    __shared__ float xs[4][IN_DIM];
    int row0 = blockIdx.x * 4;
    int t = threadIdx.x & 63;
    int r = threadIdx.x >> 6;

    for (int i = threadIdx.x; i < 4 * IN_DIM; i += 256) {
        int rr = i >> 7, cc = i & 127;
        int row = row0 + rr;
        xs[rr][cc] = (row < N_NODES) ? x[row * IN_DIM + cc] : 0.f;
    }
    __syncthreads();

    int row = row0 + r;
    if (row >= N_NODES) return;

    float acc = 0.f;
#pragma unroll 16
    for (int k = 0; k < IN_DIM; k++)
        acc += xs[r][k] * W1[k * HID + t];

    g_h1[row * HID + t] = acc * g_dinv[row];
}

// ---------------------------------------------------------------------------
// Layer-1 aggregation: one warp per dst node. Lane covers cols {lane, lane+32}.
// acc init = hs1[n] (self loop); z = relu(dinv[n]*acc + b1).
__global__ void k_agg1(const float* __restrict__ b1) {
    int w = (blockIdx.x * blockDim.x + threadIdx.x) >> 5;
    if (w >= N_NODES) return;
    int lane = threadIdx.x & 31;
    int n = w;

    const float* h = g_h1;
    float acc0 = h[n * HID + lane];
    float acc1 = h[n * HID + 32 + lane];

    int e = g_off[n];
    int end = e + g_cnt[n];
    for (; e + 2 <= end; e += 2) {
        int s0 = g_esrc[e];
        int s1 = g_esrc[e + 1];
        float a0 = h[s0 * HID + lane];
        float a1 = h[s0 * HID + 32 + lane];
        float c0 = h[s1 * HID + lane];
        float c1 = h[s1 * HID + 32 + lane];
        acc0 += a0 + c0;
        acc1 += a1 + c1;
    }
    if (e < end) {
        int s = g_esrc[e];
        acc0 += h[s * HID + lane];
        acc1 += h[s * HID + 32 + lane];
    }

    float dv = g_dinv[n];
    float z0 = fmaxf(dv * acc0 + b1[lane], 0.f);
    float z1 = fmaxf(dv * acc1 + b1[32 + lane], 0.f);
    g_z[n * HID + lane]      = z0;
    g_z[n * HID + 32 + lane] = z1;
}

// ---------------------------------------------------------------------------
// hs2 = (z @ W2) * dinv[row].  block = 256 = 16 rows x 16 cols
__global__ void k_gemm2(const float* __restrict__ W2) {
    __shared__ float zs[16][HID];
    int row0 = blockIdx.x * 16;
    int t = threadIdx.x & 15;
    int r = threadIdx.x >> 4;

    for (int i = threadIdx.x; i < 16 * HID; i += 256) {
        int rr = i >> 6, cc = i & 63;
        int row = row0 + rr;
        zs[rr][cc] = (row < N_NODES) ? g_z[row * HID + cc] : 0.f;
    }
    __syncthreads();

    int row = row0 + r;
    if (row >= N_NODES) return;

    float acc = 0.f;
#pragma unroll
    for (int k = 0; k < HID; k++)
        acc += zs[r][k] * W2[k * OUT_DIM + t];

    g_h2[row * OUT_DIM + t] = acc * g_dinv[row];
}

// ---------------------------------------------------------------------------
// Layer-2 aggregation: one warp per dst node; two half-warps each take
// alternate edges (col = lane&15), fold with shfl, write out once.
__global__ void k_agg2(float* __restrict__ out, const float* __restrict__ b2) {
    int w = (blockIdx.x * blockDim.x + threadIdx.x) >> 5;
    if (w >= N_NODES) return;
    int lane = threadIdx.x & 31;
    int col  = lane & 15;
    int hh   = lane >> 4;
    int n = w;

    float acc = (hh == 0) ? g_h2[n * OUT_DIM + col] : 0.f;  // self loop

    int beg = g_off[n];
    int end = beg + g_cnt[n];
    for (int e = beg + hh; e < end; e += 2) {
        int s = g_esrc[e];
        acc += g_h2[s * OUT_DIM + col];
    }
    acc += __shfl_xor_sync(0xffffffffu, acc, 16);

    if (hh == 0)
        out[n * OUT_DIM + col] = g_dinv[n] * acc + b2[col];
}

// ---------------------------------------------------------------------------
extern "C" void kernel_launch(void* const* d_in, const int* in_sizes, int n_in,
                              void* d_out, int out_size) {
    const float* x  = (const float*)d_in[0];
    const int*   ei = (const int*)d_in[1];    // [2, E] int32 (JAX default x32!)
    const float* W1 = (const float*)d_in[2];
    const float* b1 = (const float*)d_in[3];
    const float* W2 = (const float*)d_in[4];
    const float* b2 = (const float*)d_in[5];
    float* out = (float*)d_out;

    const int* src = ei;
    const int* dst = ei + N_EDGES;

    // CSR build
    k_zero      <<<NCHUNK, 256>>>();
    k_count     <<<(N_EDGES + 255) / 256, 256>>>(dst);
    k_scan_local<<<NCHUNK, 256>>>();
    k_scan_spine<<<1, 256>>>();
    k_scan_add  <<<NCHUNK, 256>>>();
    k_fill      <<<(N_EDGES + 255) / 256, 256>>>(src, dst);

    // Layer 1
    k_gemm1<<<(N_NODES + 3) / 4, 256>>>(x, W1);
    k_agg1 <<<(N_NODES * 32 + 255) / 256, 256>>>(b1);

    // Layer 2
    k_gemm2<<<(N_NODES + 15) / 16, 256>>>(W2);
    k_agg2 <<<(N_NODES * 32 + 255) / 256, 256>>>(out, b2);
}

// round 9
// speedup vs baseline: 1.2726x; 1.2726x over previous
#include <cuda_runtime.h>
#include <cstdint>

#define N_NODES 50000
#define N_EDGES 1000000
#define IN_DIM  128
#define HID     64
#define OUT_DIM 16
#define NCHUNK  ((N_NODES + 255) / 256)   // 196

// Scratch (device globals — no allocation allowed)
__device__ __align__(16) int   g_cnt[N_NODES];
__device__ __align__(16) int   g_off[N_NODES];
__device__ __align__(16) int   g_cur[N_NODES];
__device__ __align__(16) int   g_spine[NCHUNK];
__device__ __align__(16) int   g_esrc[N_EDGES];
__device__ __align__(16) float g_dinv[N_NODES];
__device__ __align__(16) float g_h1[N_NODES * HID];
__device__ __align__(16) float g_z [N_NODES * HID];
__device__ __align__(16) float g_h2[N_NODES * OUT_DIM];

// ---- packed fp32x2 helpers (sm_103a dual-rate fp32) -----------------------
__device__ __forceinline__ unsigned long long pk2(float lo, float hi) {
    unsigned long long r;
    asm("mov.b64 %0,{%1,%2};" : "=l"(r) : "f"(lo), "f"(hi));
    return r;
}
__device__ __forceinline__ void upk2(unsigned long long v, float& lo, float& hi) {
    asm("mov.b64 {%0,%1},%2;" : "=f"(lo), "=f"(hi) : "l"(v));
}
__device__ __forceinline__ unsigned long long fma2(unsigned long long a,
                                                   unsigned long long b,
                                                   unsigned long long c) {
    unsigned long long d;
    asm("fma.rn.f32x2 %0,%1,%2,%3;" : "=l"(d) : "l"(a), "l"(b), "l"(c));
    return d;
}

// ---------------------------------------------------------------------------
__global__ void k_zero() {
    int i = blockIdx.x * blockDim.x + threadIdx.x;
    if (i < N_NODES) g_cnt[i] = 0;
}

__global__ void k_count(const int* __restrict__ dst) {
    int e = blockIdx.x * blockDim.x + threadIdx.x;
    if (e < N_EDGES) atomicAdd(&g_cnt[dst[e]], 1);
}

__global__ void k_scan_local() {
    __shared__ int sh[256];
    int t = threadIdx.x;
    int i = blockIdx.x * 256 + t;
    int c = (i < N_NODES) ? g_cnt[i] : 0;
    sh[t] = c;
    __syncthreads();
#pragma unroll
    for (int d = 1; d < 256; d <<= 1) {
        int v = (t >= d) ? sh[t - d] : 0;
        __syncthreads();
        sh[t] += v;
        __syncthreads();
    }
    if (i < N_NODES) {
        g_off[i]  = sh[t] - c;
        g_dinv[i] = rsqrtf((float)(c + 1));
    }
    if (t == 255) g_spine[blockIdx.x] = sh[255];
}

__global__ void k_scan_spine() {
    __shared__ int sh[256];
    int t = threadIdx.x;
    int c = (t < NCHUNK) ? g_spine[t] : 0;
    sh[t] = c;
    __syncthreads();
#pragma unroll
    for (int d = 1; d < 256; d <<= 1) {
        int v = (t >= d) ? sh[t - d] : 0;
        __syncthreads();
        sh[t] += v;
        __syncthreads();
    }
    if (t < NCHUNK) g_spine[t] = sh[t] - c;
}

__global__ void k_scan_add() {
    int i = blockIdx.x * blockDim.x + threadIdx.x;
    if (i < N_NODES) {
        int o = g_off[i] + g_spine[i >> 8];
        g_off[i] = o;
        g_cur[i] = o;
    }
}

__global__ void k_fill(const int* __restrict__ src,
                       const int* __restrict__ dst) {
    int e = blockIdx.x * blockDim.x + threadIdx.x;
    if (e < N_EDGES) {
        int p = atomicAdd(&g_cur[dst[e]], 1);
        g_esrc[p] = src[e];
    }
}

// ---------------------------------------------------------------------------
// GEMM1: hs1 = (x @ W1) * dinv[row]
// Tile 64 rows x 64 cols, 256 threads. xs transposed in smem: xs[k][row].
// Thread: col = tid&63, group = tid>>6 owns rows [grp*16, grp*16+16) as 8
// packed row-pairs. Inner k-loop: 4x LDS.128 (warp-uniform broadcast) +
// 1 LDG W1 (L1-resident) + 8 fma.rn.f32x2 -> FFMA2-bound.
__global__ void __launch_bounds__(256) k_gemm1(const float* __restrict__ x,
                                               const float* __restrict__ W1) {
    __shared__ float xs[IN_DIM * 64];   // [k][row], 32 KB
    int row0 = blockIdx.x * 64;
    int tid = threadIdx.x;

    // Transposed load: lanes own consecutive rows -> conflict-free STS.
#pragma unroll
    for (int i = 0; i < 8; i++) {
        int idx = tid + i * 256;
        int row = idx & 63;
        int k0  = (idx >> 6) * 4;
        int grow = row0 + row;
        float4 v = make_float4(0.f, 0.f, 0.f, 0.f);
        if (grow < N_NODES)
            v = *reinterpret_cast<const float4*>(&x[grow * IN_DIM + k0]);
        xs[(k0 + 0) * 64 + row] = v.x;
        xs[(k0 + 1) * 64 + row] = v.y;
        xs[(k0 + 2) * 64 + row] = v.z;
        xs[(k0 + 3) * 64 + row] = v.w;
    }
    __syncthreads();

    int col = tid & 63;
    int grp = tid >> 6;
    int rbase = grp * 16;   // rows rbase..rbase+15 = pairs 0..7

    unsigned long long acc[8];
#pragma unroll
    for (int p = 0; p < 8; p++) acc[p] = 0ull;

#pragma unroll 4
    for (int k = 0; k < IN_DIM; k++) {
        float wv = W1[k * HID + col];
        unsigned long long wp = pk2(wv, wv);
        const float* base = &xs[k * 64 + rbase];
#pragma unroll
        for (int q = 0; q < 4; q++) {
            ulonglong2 u = *reinterpret_cast<const ulonglong2*>(base + q * 4);
            acc[q * 2 + 0] = fma2(u.x, wp, acc[q * 2 + 0]);
            acc[q * 2 + 1] = fma2(u.y, wp, acc[q * 2 + 1]);
        }
    }

#pragma unroll
    for (int p = 0; p < 8; p++) {
        float v0, v1;
        upk2(acc[p], v0, v1);
        int r0 = row0 + rbase + p * 2;
        if (r0 < N_NODES)     g_h1[r0 * HID + col]       = v0 * g_dinv[r0];
        if (r0 + 1 < N_NODES) g_h1[(r0 + 1) * HID + col] = v1 * g_dinv[r0 + 1];
    }
}

// ---------------------------------------------------------------------------
// Layer-1 aggregation: one warp per dst node, lane owns float2 (cols 2l,2l+1).
// 4-edge unroll -> 4 independent LDG.64 in flight.
__global__ void k_agg1(const float* __restrict__ b1) {
    int w = (blockIdx.x * blockDim.x + threadIdx.x) >> 5;
    if (w >= N_NODES) return;
    int lane = threadIdx.x & 31;

    const float2* h = reinterpret_cast<const float2*>(g_h1);
    float2 acc = h[w * 32 + lane];            // self loop

    int e = g_off[w];
    int end = e + g_cnt[w];
    for (; e + 4 <= end; e += 4) {
        int s0 = g_esrc[e], s1 = g_esrc[e + 1];
        int s2 = g_esrc[e + 2], s3 = g_esrc[e + 3];
        float2 a = h[s0 * 32 + lane];
        float2 b = h[s1 * 32 + lane];
        float2 c = h[s2 * 32 + lane];
        float2 d = h[s3 * 32 + lane];
        acc.x += (a.x + b.x) + (c.x + d.x);
        acc.y += (a.y + b.y) + (c.y + d.y);
    }
    for (; e < end; e++) {
        float2 a = h[g_esrc[e] * 32 + lane];
        acc.x += a.x;
        acc.y += a.y;
    }

    float dv = g_dinv[w];
    float2 bb = reinterpret_cast<const float2*>(b1)[lane];
    float2 z;
    z.x = fmaxf(dv * acc.x + bb.x, 0.f);
    z.y = fmaxf(dv * acc.y + bb.y, 0.f);
    reinterpret_cast<float2*>(g_z)[w * 32 + lane] = z;
}

// ---------------------------------------------------------------------------
// GEMM2: hs2 = (z @ W2) * dinv[row]
// Tile 128 rows x 16 cols, 256 threads. zs transposed [k][row], 32 KB.
// Thread: col = tid&15, grp = tid>>4 owns 8 rows = 4 packed pairs.
__global__ void __launch_bounds__(256) k_gemm2(const float* __restrict__ W2) {
    __shared__ float zs[HID * 128];   // [k][row], 32 KB
    int row0 = blockIdx.x * 128;
    int tid = threadIdx.x;

#pragma unroll
    for (int i = 0; i < 8; i++) {
        int idx = tid + i * 256;
        int row = idx & 127;
        int k0  = (idx >> 7) * 4;
        int grow = row0 + row;
        float4 v = make_float4(0.f, 0.f, 0.f, 0.f);
        if (grow < N_NODES)
            v = *reinterpret_cast<const float4*>(&g_z[grow * HID + k0]);
        zs[(k0 + 0) * 128 + row] = v.x;
        zs[(k0 + 1) * 128 + row] = v.y;
        zs[(k0 + 2) * 128 + row] = v.z;
        zs[(k0 + 3) * 128 + row] = v.w;
    }
    __syncthreads();

    int col = tid & 15;
    int grp = tid >> 4;
    int rbase = grp * 8;   // 8 rows = 4 pairs

    unsigned long long acc[4];
#pragma unroll
    for (int p = 0; p < 4; p++) acc[p] = 0ull;

#pragma unroll 4
    for (int k = 0; k < HID; k++) {
        float wv = W2[k * OUT_DIM + col];
        unsigned long long wp = pk2(wv, wv);
        const float* base = &zs[k * 128 + rbase];
#pragma unroll
        for (int q = 0; q < 2; q++) {
            ulonglong2 u = *reinterpret_cast<const ulonglong2*>(base + q * 4);
            acc[q * 2 + 0] = fma2(u.x, wp, acc[q * 2 + 0]);
            acc[q * 2 + 1] = fma2(u.y, wp, acc[q * 2 + 1]);
        }
    }

#pragma unroll
    for (int p = 0; p < 4; p++) {
        float v0, v1;
        upk2(acc[p], v0, v1);
        int r0 = row0 + rbase + p * 2;
        if (r0 < N_NODES)     g_h2[r0 * OUT_DIM + col]       = v0 * g_dinv[r0];
        if (r0 + 1 < N_NODES) g_h2[(r0 + 1) * OUT_DIM + col] = v1 * g_dinv[r0 + 1];
    }
}

// ---------------------------------------------------------------------------
// Layer-2 aggregation: one warp per node; half-warps take alternate edges
// (2-edge unroll per half = 4 loads in flight), shfl-fold, single write.
__global__ void k_agg2(float* __restrict__ out, const float* __restrict__ b2) {
    int w = (blockIdx.x * blockDim.x + threadIdx.x) >> 5;
    if (w >= N_NODES) return;
    int lane = threadIdx.x & 31;
    int col  = lane & 15;
    int hh   = lane >> 4;

    float acc = (hh == 0) ? g_h2[w * OUT_DIM + col] : 0.f;   // self loop

    int beg = g_off[w];
    int end = beg + g_cnt[w];
    int e = beg + hh;
    for (; e + 2 < end; e += 4) {   // this half's edges: e, e+2
        int s0 = g_esrc[e];
        int s1 = g_esrc[e + 2];
        float a = g_h2[s0 * OUT_DIM + col];
        float b = g_h2[s1 * OUT_DIM + col];
        acc += a + b;
    }
    if (e < end)
        acc += g_h2[g_esrc[e] * OUT_DIM + col];

    acc += __shfl_xor_sync(0xffffffffu, acc, 16);

    if (hh == 0)
        out[w * OUT_DIM + col] = g_dinv[w] * acc + b2[col];
}

// ---------------------------------------------------------------------------
extern "C" void kernel_launch(void* const* d_in, const int* in_sizes, int n_in,
                              void* d_out, int out_size) {
    const float* x  = (const float*)d_in[0];
    const int*   ei = (const int*)d_in[1];    // [2, E] int32 (JAX x32 default)
    const float* W1 = (const float*)d_in[2];
    const float* b1 = (const float*)d_in[3];
    const float* W2 = (const float*)d_in[4];
    const float* b2 = (const float*)d_in[5];
    float* out = (float*)d_out;

    const int* src = ei;
    const int* dst = ei + N_EDGES;

    // CSR build
    k_zero      <<<NCHUNK, 256>>>();
    k_count     <<<(N_EDGES + 255) / 256, 256>>>(dst);
    k_scan_local<<<NCHUNK, 256>>>();
    k_scan_spine<<<1, 256>>>();
    k_scan_add  <<<NCHUNK, 256>>>();
    k_fill      <<<(N_EDGES + 255) / 256, 256>>>(src, dst);

    // Layer 1
    k_gemm1<<<(N_NODES + 63) / 64, 256>>>(x, W1);
    k_agg1 <<<(N_NODES * 32 + 255) / 256, 256>>>(b1);

    // Layer 2
    k_gemm2<<<(N_NODES + 127) / 128, 256>>>(W2);
    k_agg2 <<<(N_NODES * 32 + 255) / 256, 256>>>(out, b2);
}

// round 10
// speedup vs baseline: 1.4152x; 1.1121x over previous
#include <cuda_runtime.h>
#include <cstdint>

#define N_NODES 50000
#define N_EDGES 1000000
#define IN_DIM  128
#define HID     64
#define OUT_DIM 16
#define NCHUNK  ((N_NODES + 255) / 256)   // 196

// Scratch (device globals — no allocation allowed)
__device__ int g_total;
__device__ __align__(16) int   g_cnt[N_NODES];
__device__ __align__(16) int   g_off[N_NODES];
__device__ __align__(16) int   g_cur[N_NODES];
__device__ __align__(16) int   g_esrc[N_EDGES];
__device__ __align__(16) float g_dinv[N_NODES];
__device__ __align__(16) float g_h1[N_NODES * HID];     // x@W1 (UNscaled)
__device__ __align__(16) float g_z [N_NODES * HID];     // relu(dinv*agg1 + b1)
__device__ __align__(16) float g_h2[N_NODES * OUT_DIM]; // (z@W2)*dinv[row]

// ---- packed fp32x2 helpers (sm_103a dual-rate fp32) -----------------------
__device__ __forceinline__ unsigned long long pk2(float lo, float hi) {
    unsigned long long r;
    asm("mov.b64 %0,{%1,%2};" : "=l"(r) : "f"(lo), "f"(hi));
    return r;
}
__device__ __forceinline__ void upk2(unsigned long long v, float& lo, float& hi) {
    asm("mov.b64 {%0,%1},%2;" : "=f"(lo), "=f"(hi) : "l"(v));
}
__device__ __forceinline__ unsigned long long fma2(unsigned long long a,
                                                   unsigned long long b,
                                                   unsigned long long c) {
    unsigned long long d;
    asm("fma.rn.f32x2 %0,%1,%2,%3;" : "=l"(d) : "l"(a), "l"(b), "l"(c));
    return d;
}

// ---------------------------------------------------------------------------
__global__ void k_zero() {
    int i = blockIdx.x * blockDim.x + threadIdx.x;
    if (i < N_NODES) g_cnt[i] = 0;
    if (i == 0) g_total = 0;
}

__global__ void k_count(const int* __restrict__ dst) {
    int e = blockIdx.x * blockDim.x + threadIdx.x;
    if (e < N_EDGES) atomicAdd(&g_cnt[dst[e]], 1);
}

// Single-pass offsets: block scan + atomic chunk base (buckets need only be
// disjoint, not ordered by node id). Also computes dinv.
__global__ void k_offsets() {
    __shared__ int sh[256];
    __shared__ int base;
    int t = threadIdx.x;
    int i = blockIdx.x * 256 + t;
    int c = (i < N_NODES) ? g_cnt[i] : 0;
    sh[t] = c;
    __syncthreads();
#pragma unroll
    for (int d = 1; d < 256; d <<= 1) {
        int v = (t >= d) ? sh[t - d] : 0;
        __syncthreads();
        sh[t] += v;
        __syncthreads();
    }
    if (t == 255) base = atomicAdd(&g_total, sh[255]);
    __syncthreads();
    if (i < N_NODES) {
        int o = base + sh[t] - c;
        g_off[i]  = o;
        g_cur[i]  = o;
        g_dinv[i] = rsqrtf((float)(c + 1));   // deg includes self loop
    }
}

__global__ void k_fill(const int* __restrict__ src,
                       const int* __restrict__ dst) {
    int e = blockIdx.x * blockDim.x + threadIdx.x;
    if (e < N_EDGES) {
        int p = atomicAdd(&g_cur[dst[e]], 1);
        g_esrc[p] = src[e];
    }
}

// ---------------------------------------------------------------------------
// GEMM1: h1 = x @ W1   (no dinv — runs concurrently with the CSR build)
// Tile 64 rows x 64 cols, 256 threads; xs transposed [k][row]; FFMA2 core.
__global__ void __launch_bounds__(256) k_gemm1(const float* __restrict__ x,
                                               const float* __restrict__ W1) {
    __shared__ float xs[IN_DIM * 64];   // 32 KB
    int row0 = blockIdx.x * 64;
    int tid = threadIdx.x;

#pragma unroll
    for (int i = 0; i < 8; i++) {
        int idx = tid + i * 256;
        int row = idx & 63;
        int k0  = (idx >> 6) * 4;
        int grow = row0 + row;
        float4 v = make_float4(0.f, 0.f, 0.f, 0.f);
        if (grow < N_NODES)
            v = *reinterpret_cast<const float4*>(&x[grow * IN_DIM + k0]);
        xs[(k0 + 0) * 64 + row] = v.x;
        xs[(k0 + 1) * 64 + row] = v.y;
        xs[(k0 + 2) * 64 + row] = v.z;
        xs[(k0 + 3) * 64 + row] = v.w;
    }
    __syncthreads();

    int col = tid & 63;
    int grp = tid >> 6;
    int rbase = grp * 16;

    unsigned long long acc[8];
#pragma unroll
    for (int p = 0; p < 8; p++) acc[p] = 0ull;

#pragma unroll 4
    for (int k = 0; k < IN_DIM; k++) {
        float wv = W1[k * HID + col];
        unsigned long long wp = pk2(wv, wv);
        const float* base = &xs[k * 64 + rbase];
#pragma unroll
        for (int q = 0; q < 4; q++) {
            ulonglong2 u = *reinterpret_cast<const ulonglong2*>(base + q * 4);
            acc[q * 2 + 0] = fma2(u.x, wp, acc[q * 2 + 0]);
            acc[q * 2 + 1] = fma2(u.y, wp, acc[q * 2 + 1]);
        }
    }

#pragma unroll
    for (int p = 0; p < 8; p++) {
        float v0, v1;
        upk2(acc[p], v0, v1);
        int r0 = row0 + rbase + p * 2;
        if (r0 < N_NODES)     g_h1[r0 * HID + col]       = v0;
        if (r0 + 1 < N_NODES) g_h1[(r0 + 1) * HID + col] = v1;
    }
}

// ---------------------------------------------------------------------------
// Layer-1 aggregation: one warp per dst node, lane owns float2.
// acc = dinv[n]*h1[n] + sum dinv[s]*h1[s]; z = relu(dinv[n]*acc + b1).
// 8-edge unroll -> 16 gathers in flight.
__global__ void k_agg1(const float* __restrict__ b1) {
    int w = (blockIdx.x * blockDim.x + threadIdx.x) >> 5;
    if (w >= N_NODES) return;
    int lane = threadIdx.x & 31;

    const float2* h = reinterpret_cast<const float2*>(g_h1);
    float dv = g_dinv[w];
    float2 hw = h[w * 32 + lane];
    float2 acc;
    acc.x = dv * hw.x;                        // self loop
    acc.y = dv * hw.y;

    int e = g_off[w];
    int end = e + g_cnt[w];
    for (; e + 8 <= end; e += 8) {
        int s[8];
#pragma unroll
        for (int j = 0; j < 8; j++) s[j] = g_esrc[e + j];
        float dd[8]; float2 v[8];
#pragma unroll
        for (int j = 0; j < 8; j++) { dd[j] = g_dinv[s[j]]; v[j] = h[s[j] * 32 + lane]; }
#pragma unroll
        for (int j = 0; j < 8; j++) { acc.x += dd[j] * v[j].x; acc.y += dd[j] * v[j].y; }
    }
    for (; e < end; e++) {
        int s = g_esrc[e];
        float dd = g_dinv[s];
        float2 v = h[s * 32 + lane];
        acc.x += dd * v.x;
        acc.y += dd * v.y;
    }

    float2 bb = reinterpret_cast<const float2*>(b1)[lane];
    float2 z;
    z.x = fmaxf(dv * acc.x + bb.x, 0.f);
    z.y = fmaxf(dv * acc.y + bb.y, 0.f);
    reinterpret_cast<float2*>(g_z)[w * 32 + lane] = z;
}

// ---------------------------------------------------------------------------
// GEMM2: hs2 = (z @ W2) * dinv[row].  Tile 128x16, FFMA2 core.
__global__ void __launch_bounds__(256) k_gemm2(const float* __restrict__ W2) {
    __shared__ float zs[HID * 128];   // 32 KB
    int row0 = blockIdx.x * 128;
    int tid = threadIdx.x;

#pragma unroll
    for (int i = 0; i < 8; i++) {
        int idx = tid + i * 256;
        int row = idx & 127;
        int k0  = (idx >> 7) * 4;
        int grow = row0 + row;
        float4 v = make_float4(0.f, 0.f, 0.f, 0.f);
        if (grow < N_NODES)
            v = *reinterpret_cast<const float4*>(&g_z[grow * HID + k0]);
        zs[(k0 + 0) * 128 + row] = v.x;
        zs[(k0 + 1) * 128 + row] = v.y;
        zs[(k0 + 2) * 128 + row] = v.z;
        zs[(k0 + 3) * 128 + row] = v.w;
    }
    __syncthreads();

    int col = tid & 15;
    int grp = tid >> 4;
    int rbase = grp * 8;

    unsigned long long acc[4];
#pragma unroll
    for (int p = 0; p < 4; p++) acc[p] = 0ull;

#pragma unroll 4
    for (int k = 0; k < HID; k++) {
        float wv = W2[k * OUT_DIM + col];
        unsigned long long wp = pk2(wv, wv);
        const float* base = &zs[k * 128 + rbase];
#pragma unroll
        for (int q = 0; q < 2; q++) {
            ulonglong2 u = *reinterpret_cast<const ulonglong2*>(base + q * 4);
            acc[q * 2 + 0] = fma2(u.x, wp, acc[q * 2 + 0]);
            acc[q * 2 + 1] = fma2(u.y, wp, acc[q * 2 + 1]);
        }
    }

#pragma unroll
    for (int p = 0; p < 4; p++) {
        float v0, v1;
        upk2(acc[p], v0, v1);
        int r0 = row0 + rbase + p * 2;
        if (r0 < N_NODES)     g_h2[r0 * OUT_DIM + col]       = v0 * g_dinv[r0];
        if (r0 + 1 < N_NODES) g_h2[(r0 + 1) * OUT_DIM + col] = v1 * g_dinv[r0 + 1];
    }
}

// ---------------------------------------------------------------------------
// Layer-2 aggregation: one warp per node; half-warps take alternate edges,
// 4-edge unroll per half (8 loads in flight), shfl-fold, single write.
__global__ void k_agg2(float* __restrict__ out, const float* __restrict__ b2) {
    int w = (blockIdx.x * blockDim.x + threadIdx.x) >> 5;
    if (w >= N_NODES) return;
    int lane = threadIdx.x & 31;
    int col  = lane & 15;
    int hh   = lane >> 4;

    float acc = (hh == 0) ? g_h2[w * OUT_DIM + col] : 0.f;   // self loop

    int beg = g_off[w];
    int end = beg + g_cnt[w];
    int e = beg + hh;
    for (; e + 6 < end; e += 8) {   // this half's edges: e, e+2, e+4, e+6
        int s0 = g_esrc[e];
        int s1 = g_esrc[e + 2];
        int s2 = g_esrc[e + 4];
        int s3 = g_esrc[e + 6];
        float a = g_h2[s0 * OUT_DIM + col];
        float b = g_h2[s1 * OUT_DIM + col];
        float c = g_h2[s2 * OUT_DIM + col];
        float d = g_h2[s3 * OUT_DIM + col];
        acc += (a + b) + (c + d);
    }
    for (; e < end; e += 2)
        acc += g_h2[g_esrc[e] * OUT_DIM + col];

    acc += __shfl_xor_sync(0xffffffffu, acc, 16);

    if (hh == 0)
        out[w * OUT_DIM + col] = g_dinv[w] * acc + b2[col];
}

// ---------------------------------------------------------------------------
extern "C" void kernel_launch(void* const* d_in, const int* in_sizes, int n_in,
                              void* d_out, int out_size) {
    const float* x  = (const float*)d_in[0];
    const int*   ei = (const int*)d_in[1];    // [2, E] int32 (JAX x32 default)
    const float* W1 = (const float*)d_in[2];
    const float* b1 = (const float*)d_in[3];
    const float* W2 = (const float*)d_in[4];
    const float* b2 = (const float*)d_in[5];
    float* out = (float*)d_out;

    const int* src = ei;
    const int* dst = ei + N_EDGES;

    // Fork a side stream so gemm1 (independent of the CSR build) overlaps it.
    cudaStream_t s2 = 0;
    cudaEvent_t evF = 0, evJ = 0;
    bool forked = (cudaStreamCreateWithFlags(&s2, cudaStreamNonBlocking) == cudaSuccess) &&
                  (cudaEventCreateWithFlags(&evF, cudaEventDisableTiming) == cudaSuccess) &&
                  (cudaEventCreateWithFlags(&evJ, cudaEventDisableTiming) == cudaSuccess);

    if (forked) {
        cudaEventRecord(evF, 0);
        cudaStreamWaitEvent(s2, evF, 0);
        k_gemm1<<<(N_NODES + 63) / 64, 256, 0, s2>>>(x, W1);
        cudaEventRecord(evJ, s2);
    } else {
        k_gemm1<<<(N_NODES + 63) / 64, 256>>>(x, W1);
    }

    // CSR build (default stream, concurrent with gemm1)
    k_zero   <<<NCHUNK, 256>>>();
    k_count  <<<(N_EDGES + 255) / 256, 256>>>(dst);
    k_offsets<<<NCHUNK, 256>>>();
    k_fill   <<<(N_EDGES + 255) / 256, 256>>>(src, dst);

    if (forked) cudaStreamWaitEvent(0, evJ, 0);

    // Layer 1 aggregation, then layer 2
    k_agg1 <<<(N_NODES * 32 + 255) / 256, 256>>>(b1);
    k_gemm2<<<(N_NODES + 127) / 128, 256>>>(W2);
    k_agg2 <<<(N_NODES * 32 + 255) / 256, 256>>>(out, b2);

    if (forked) {
        cudaEventDestroy(evF);
        cudaEventDestroy(evJ);
        cudaStreamDestroy(s2);
    }
}